// round 3
// baseline (speedup 1.0000x reference)
#include <cuda_runtime.h>
#include <math.h>

#define WPB 4
#define FULL 0xffffffffu
#define INVS10 0.31622776601683794f   // 1/sqrt(10)
#define EPS_ 1e-4f

struct WarpSmem {
    float2 HY[9][18];  // whitened columns, column-major padded: HY[j][m]
    float2 g[8][9];    // Gram g[i][j]; column 8 = ymf
    float2 u[8];       // ymf - g*x
    float2 Mc[8];      // (W g)[s][s]
    float2 Wu[8];      // (W u)[s]
};

__global__ __launch_bounds__(128, 9)
void mmse_pic_kernel(const float* __restrict__ y_re, const float* __restrict__ y_im,
                     const float* __restrict__ h_re, const float* __restrict__ h_im,
                     const float* __restrict__ prior,
                     const float* __restrict__ s_re, const float* __restrict__ s_im,
                     float* __restrict__ out, int nbatch)
{
    const int warp = threadIdx.x >> 5;
    const int lane = threadIdx.x & 31;
    const int b = blockIdx.x * WPB + warp;

    __shared__ WarpSmem ws[WPB];
    if (b >= nbatch) return;
    WarpSmem& w = ws[warp];

    // ---------------- direct strided column loads (coalesced across lanes) ----------------
    // lane 0..15 : column `lane` of S   (stride 16)
    // lane 16..23: column `lane-16` of H (stride 8)
    // lane 24..31: y                     (stride 1)
    float ar[16], ai[16];
    {
        const float *br, *bi;
        int stride;
        if (lane < 16)      { br = s_re + (size_t)b * 256 + lane;        bi = s_im + (size_t)b * 256 + lane;        stride = 16; }
        else if (lane < 24) { br = h_re + (size_t)b * 128 + (lane - 16); bi = h_im + (size_t)b * 128 + (lane - 16); stride = 8;  }
        else                { br = y_re + (size_t)b * 16;                bi = y_im + (size_t)b * 16;                stride = 1;  }
        #pragma unroll
        for (int m = 0; m < 16; m++) {
            ar[m] = br[m * stride];
            ai[m] = bi[m * stride];
        }
    }
    // prior LLRs: lane s<8 keeps its 4 bits in registers
    float l0 = 0.f, l1 = 0.f, l2 = 0.f, l3 = 0.f;
    if (lane < 8) {
        float4 p = *(const float4*)(prior + (size_t)b * 32 + lane * 4);
        l0 = p.x; l1 = p.y; l2 = p.z; l3 = p.w;
    }

    // ---------------- forward Gaussian elimination on [S | H | y] ----------------
    // S = L D L^H ; pivots d_k real > 0. Row-k scaled by rsqrt(d_k) afterwards
    // gives Cholesky-whitened [Hw | yw] in lanes 16..24.
    #pragma unroll
    for (int k = 0; k < 16; k++) {
        float dk = __shfl_sync(FULL, ar[k], k);
        float invd = __fdividef(1.0f, dk);
        float rsd = rsqrtf(dk);
        #pragma unroll
        for (int i = k + 1; i < 16; i++) {
            float mr = __shfl_sync(FULL, ar[i], k) * invd;
            float mi = __shfl_sync(FULL, ai[i], k) * invd;
            ar[i] = fmaf(-mr, ar[k], fmaf( mi, ai[k], ar[i]));
            ai[i] = fmaf(-mr, ai[k], fmaf(-mi, ar[k], ai[i]));
        }
        ar[k] *= rsd; ai[k] *= rsd;
    }

    // write whitened [H | y] columns (float4, conflict-free: bank offset 4j)
    if (lane >= 16 && lane < 25) {
        int j = lane - 16;
        #pragma unroll
        for (int m = 0; m < 16; m += 2)
            *(float4*)&w.HY[j][m] = make_float4(ar[m], ai[m], ar[m + 1], ai[m + 1]);
    }
    __syncwarp();

    // ---------------- Gram g = Hw^H Hw (8x8) and ymf = Hw^H yw (column 8) ----------------
    #pragma unroll
    for (int r = 0; r < 3; r++) {
        int t = lane + 32 * r;
        if (t < 72) {
            int i = t / 9, j = t - 9 * i;
            float re = 0.f, im = 0.f;
            #pragma unroll
            for (int m = 0; m < 16; m += 2) {
                float4 a4 = *(const float4*)&w.HY[i][m];
                float4 c4 = *(const float4*)&w.HY[j][m];
                re = fmaf(a4.x, c4.x, fmaf(a4.y, c4.y, re));
                im = fmaf(a4.x, c4.y, fmaf(-a4.y, c4.x, im));
                re = fmaf(a4.z, c4.z, fmaf(a4.w, c4.w, re));
                im = fmaf(a4.z, c4.w, fmaf(-a4.w, c4.z, im));
            }
            w.g[i][j] = make_float2(re, im);
        }
    }
    __syncwarp();

    // ---------------- MMSE-PIC iterations ----------------
    float d0 = 0.f, d1 = 0.f, d2 = 0.f, d3 = 0.f;       // llr_d
    float pa0 = 0.f, pa1 = 0.f, pa2 = 0.f, pa3 = 0.f;   // llr_a (final iter)

    #pragma unroll 1
    for (int iter = 0; iter < 2; iter++) {
        // (a) soft-symbol moments via per-bit factorization (4 sigmoids, no softmax)
        float s0 = __fdividef(1.f, 1.f + __expf(-l0));
        float s1 = __fdividef(1.f, 1.f + __expf(-l1));
        float s2 = __fdividef(1.f, 1.f + __expf(-l2));
        float s3 = __fdividef(1.f, 1.f + __expf(-l3));
        float mre = (1.f - 2.f * s0) * (1.f + 2.f * s2) * INVS10;
        float mim = (1.f - 2.f * s1) * (1.f + 2.f * s3) * INVS10;
        float var = (2.f + 8.f * (s2 + s3)) * 0.1f - (mre * mre + mim * mim);

        // (b) u = ymf - g @ x_hat  (lanes 0..7)
        if (lane < 8) {
            float2 acc = w.g[lane][8];   // ymf
            #pragma unroll
            for (int j = 0; j < 8; j++) {
                float xrj = __shfl_sync(0xffu, mre, j);
                float xij = __shfl_sync(0xffu, mim, j);
                float2 gij = w.g[lane][j];
                acc.x -= gij.x * xrj - gij.y * xij;
                acc.y -= gij.x * xij + gij.y * xrj;
            }
            w.u[lane] = acc;
        }
        __syncwarp();

        // (c) augmented complex system columns: [a_c | g | u], a_c = I + g*diag(var)
        float cr[8], ci[8];
        if (lane < 16) {
            int j = lane & 7;
            #pragma unroll
            for (int i = 0; i < 8; i++) {
                float2 gij = w.g[i][j];
                if (lane < 8) {
                    cr[i] = fmaf(gij.x, var, (i == j) ? 1.f : 0.f);
                    ci[i] = gij.y * var;
                } else {
                    cr[i] = gij.x; ci[i] = gij.y;
                }
            }
        } else if (lane == 16) {
            #pragma unroll
            for (int i = 0; i < 8; i++) { float2 uu = w.u[i]; cr[i] = uu.x; ci[i] = uu.y; }
        } else {
            #pragma unroll
            for (int i = 0; i < 8; i++) { cr[i] = 0.f; ci[i] = 0.f; }
        }

        // (d) 8x8 complex Gauss-Jordan; lanes 8..16 become [W g | W u]
        #pragma unroll
        for (int k = 0; k < 8; k++) {
            float dk = __shfl_sync(FULL, cr[k], k);     // pivot is real
            float invd = __fdividef(1.f, dk);
            cr[k] *= invd; ci[k] *= invd;
            #pragma unroll
            for (int i = 0; i < 8; i++) {
                if (i == k) continue;
                float mr = __shfl_sync(FULL, cr[i], k);
                float mi = __shfl_sync(FULL, ci[i], k);
                cr[i] = fmaf(-mr, cr[k], fmaf( mi, ci[k], cr[i]));
                ci[i] = fmaf(-mr, ci[k], fmaf(-mi, cr[k], ci[i]));
            }
        }

        // (e) extract Mc_s = (Wg)[s][s] and Wu
        if (lane >= 8 && lane < 16) {
            int s = lane - 8;
            float vr = 0.f, vi = 0.f;
            #pragma unroll
            for (int q = 0; q < 8; q++) if (q == s) { vr = cr[q]; vi = ci[q]; }
            w.Mc[s] = make_float2(vr, vi);
        }
        if (lane == 16) {
            #pragma unroll
            for (int s = 0; s < 8; s++) w.Wu[s] = make_float2(cr[s], ci[s]);
        }
        __syncwarp();

        // (f) finalize + separable max-log demap (lane s = stream)
        if (lane < 8) {
            float2 Mc = w.Mc[lane];
            float2 Wu = w.Wu[lane];
            float mu = Mc.x;
            float vr = Wu.x + mre * Mc.x - mim * Mc.y;
            float vi = Wu.y + mre * Mc.y + mim * Mc.x;
            float invmu = __fdividef(1.f, mu);
            float xr_ = vr * invmu, xi_ = vi * invmu;
            float rho = mu * __fdividef(1.f, fmaxf(1.f - var * mu, EPS_));

            float q1 = rho * 0.1f;
            float c1 = 2.f * INVS10 * rho * xr_;
            float RE00 =        c1 -       q1;
            float RE01 =  3.f * c1 - 9.f * q1 + l2;
            float RE10 =       -c1 -       q1 + l0;
            float RE11 = -3.f * c1 - 9.f * q1 + l0 + l2;
            d0 = fmaxf(RE10, RE11) - fmaxf(RE00, RE01);
            d2 = fmaxf(RE01, RE11) - fmaxf(RE00, RE10);
            float c2 = 2.f * INVS10 * rho * xi_;
            float IM00 =        c2 -       q1;
            float IM01 =  3.f * c2 - 9.f * q1 + l3;
            float IM10 =       -c2 -       q1 + l1;
            float IM11 = -3.f * c2 - 9.f * q1 + l1 + l3;
            d1 = fmaxf(IM10, IM11) - fmaxf(IM00, IM01);
            d3 = fmaxf(IM01, IM11) - fmaxf(IM00, IM10);
        }

        if (iter == 0) {
            pa0 = d0; pa1 = d1; pa2 = d2; pa3 = d3;
            l0 = d0; l1 = d1; l2 = d2; l3 = d3;   // llr_a <- llr_d
        }
    }

    // ---------------- extrinsic output ----------------
    if (lane < 8) {
        float4 o = make_float4(d0 - pa0, d1 - pa1, d2 - pa2, d3 - pa3);
        *(float4*)(out + (size_t)b * 32 + lane * 4) = o;
    }
}

extern "C" void kernel_launch(void* const* d_in, const int* in_sizes, int n_in,
                              void* d_out, int out_size)
{
    const float* y_re  = (const float*)d_in[0];
    const float* y_im  = (const float*)d_in[1];
    const float* h_re  = (const float*)d_in[2];
    const float* h_im  = (const float*)d_in[3];
    const float* prior = (const float*)d_in[4];
    const float* s_re  = (const float*)d_in[5];
    const float* s_im  = (const float*)d_in[6];
    float* out = (float*)d_out;

    int nbatch = in_sizes[0] / 16;   // y_re is [B, M]
    int blocks = (nbatch + WPB - 1) / WPB;
    mmse_pic_kernel<<<blocks, WPB * 32>>>(y_re, y_im, h_re, h_im, prior,
                                          s_re, s_im, out, nbatch);
}

// round 4
// speedup vs baseline: 1.6616x; 1.6616x over previous
#include <cuda_runtime.h>
#include <math.h>

#define WPB 4
#define FULL 0xffffffffu
#define INVS10 0.31622776601683794f   // 1/sqrt(10)
#define EPS_ 1e-4f

typedef unsigned long long ull;

__device__ __forceinline__ ull PK(float lo, float hi) {
    ull r; asm("mov.b64 %0, {%1,%2};" : "=l"(r) : "f"(lo), "f"(hi)); return r;
}
__device__ __forceinline__ void UPK(ull v, float& lo, float& hi) {
    asm("mov.b64 {%0,%1}, %2;" : "=f"(lo), "=f"(hi) : "l"(v));
}
__device__ __forceinline__ ull FMA2(ull a, ull b, ull c) {
    ull d; asm("fma.rn.f32x2 %0, %1, %2, %3;" : "=l"(d) : "l"(a), "l"(b), "l"(c)); return d;
}
__device__ __forceinline__ ull MUL2(ull a, ull b) {
    ull d; asm("mul.rn.f32x2 %0, %1, %2;" : "=l"(d) : "l"(a), "l"(b)); return d;
}

struct WarpSmem {
    union {
        float2 A[16][26];      // staging: [S cols 0..15 | H cols 16..23 | y col 24]
        struct {
            float2 HY[9][18];  // whitened columns, col-major padded
            float2 g[8][9];    // Gram; column 8 = ymf
            float2 u[8];
            float2 Mc[8];
            float2 Wu[8];
        } it;
    } s;
};

__global__ __launch_bounds__(128)
void mmse_pic_kernel(const float* __restrict__ y_re, const float* __restrict__ y_im,
                     const float* __restrict__ h_re, const float* __restrict__ h_im,
                     const float* __restrict__ prior,
                     const float* __restrict__ s_re, const float* __restrict__ s_im,
                     float* __restrict__ out, int nbatch)
{
    const int warp = threadIdx.x >> 5;
    const int lane = threadIdx.x & 31;
    const int b = blockIdx.x * WPB + warp;

    __shared__ WarpSmem ws[WPB];
    if (b >= nbatch) return;
    WarpSmem& w = ws[warp];

    // ---------------- coalesced staging into A = [S | H | y] (float2 interleaved) ----------------
    {
        const float* sre = s_re + (size_t)b * 256;
        const float* sim = s_im + (size_t)b * 256;
        #pragma unroll
        for (int t = lane; t < 256; t += 32)
            w.s.A[t >> 4][t & 15] = make_float2(sre[t], sim[t]);
        const float* hre = h_re + (size_t)b * 128;
        const float* him = h_im + (size_t)b * 128;
        #pragma unroll
        for (int t = lane; t < 128; t += 32)
            w.s.A[t >> 3][16 + (t & 7)] = make_float2(hre[t], him[t]);
        if (lane < 16)
            w.s.A[lane][24] = make_float2(y_re[(size_t)b * 16 + lane], y_im[(size_t)b * 16 + lane]);
    }
    // prior LLRs: lane s<8 keeps its 4 bits in registers
    float l0 = 0.f, l1 = 0.f, l2 = 0.f, l3 = 0.f;
    if (lane < 8) {
        float4 p = *(const float4*)(prior + (size_t)b * 32 + lane * 4);
        l0 = p.x; l1 = p.y; l2 = p.z; l3 = p.w;
    }
    __syncwarp();

    // ---------------- column-per-lane packed registers ----------------
    ull v[16];
    {
        int c = (lane < 25) ? lane : 24;
        #pragma unroll
        for (int m = 0; m < 16; m++) v[m] = *(const ull*)&w.s.A[m][c];
    }
    __syncwarp();   // A dead after this (aliased by it.*)

    // ---------------- forward Gaussian elimination on [S | H | y] (packed f32x2) ----------------
    // S = L D L^H, pivots real > 0. Rows scaled by rsqrt(d_k) -> Cholesky-whitened [Hw|yw].
    #pragma unroll
    for (int k = 0; k < 16; k++) {
        float vkr, vki; UPK(v[k], vkr, vki);
        float dk = __shfl_sync(FULL, vkr, k);
        float invd = __fdividef(1.0f, dk);
        float rsd = rsqrtf(dk);
        ull nwk = MUL2(v[k], PK(-invd, -invd));     // (-wr, -wi), w = invd * x_k (lane-local)
        float nwr, nwi; UPK(nwk, nwr, nwi);
        ull nwk2 = PK(-nwi, nwr);                   // (wi, -wr)
        #pragma unroll
        for (int i = k + 1; i < 16; i++) {
            float xr, xi; UPK(v[i], xr, xi);
            float rr = __shfl_sync(FULL, xr, k);
            float ri = __shfl_sync(FULL, xi, k);
            v[i] = FMA2(PK(rr, rr), nwk, v[i]);     // -= rr*w
            v[i] = FMA2(PK(ri, ri), nwk2, v[i]);    // -= ri*(i*w)
        }
        v[k] = MUL2(v[k], PK(rsd, rsd));
    }

    // write whitened [H | y] columns (float4, col-major)
    if (lane >= 16 && lane < 25) {
        int j = lane - 16;
        #pragma unroll
        for (int m = 0; m < 16; m += 2) {
            float a0, b0, a1, b1;
            UPK(v[m], a0, b0); UPK(v[m + 1], a1, b1);
            *(float4*)&w.s.it.HY[j][m] = make_float4(a0, b0, a1, b1);
        }
    }
    __syncwarp();

    // ---------------- Gram g = Hw^H Hw (8x8) and ymf = Hw^H yw (column 8) ----------------
    #pragma unroll
    for (int r = 0; r < 3; r++) {
        int t = lane + 32 * r;
        if (t < 72) {
            int i = t / 9, j = t - 9 * i;
            float re = 0.f, im = 0.f;
            #pragma unroll
            for (int m = 0; m < 16; m += 2) {
                float4 a4 = *(const float4*)&w.s.it.HY[i][m];
                float4 c4 = *(const float4*)&w.s.it.HY[j][m];
                re = fmaf(a4.x, c4.x, fmaf(a4.y, c4.y, re));
                im = fmaf(a4.x, c4.y, fmaf(-a4.y, c4.x, im));
                re = fmaf(a4.z, c4.z, fmaf(a4.w, c4.w, re));
                im = fmaf(a4.z, c4.w, fmaf(-a4.w, c4.z, im));
            }
            w.s.it.g[i][j] = make_float2(re, im);
        }
    }
    __syncwarp();

    // ---------------- MMSE-PIC iterations ----------------
    float d0 = 0.f, d1 = 0.f, d2 = 0.f, d3 = 0.f;
    float pa0 = 0.f, pa1 = 0.f, pa2 = 0.f, pa3 = 0.f;

    #pragma unroll 1
    for (int iter = 0; iter < 2; iter++) {
        // (a) soft-symbol moments via per-bit factorization
        float s0 = __fdividef(1.f, 1.f + __expf(-l0));
        float s1 = __fdividef(1.f, 1.f + __expf(-l1));
        float s2 = __fdividef(1.f, 1.f + __expf(-l2));
        float s3 = __fdividef(1.f, 1.f + __expf(-l3));
        float mre = (1.f - 2.f * s0) * (1.f + 2.f * s2) * INVS10;
        float mim = (1.f - 2.f * s1) * (1.f + 2.f * s3) * INVS10;
        float var = (2.f + 8.f * (s2 + s3)) * 0.1f - (mre * mre + mim * mim);

        // (b) u = ymf - g @ x_hat  (lanes 0..7)
        if (lane < 8) {
            float2 acc = w.s.it.g[lane][8];
            #pragma unroll
            for (int j = 0; j < 8; j++) {
                float xrj = __shfl_sync(0xffu, mre, j);
                float xij = __shfl_sync(0xffu, mim, j);
                float2 gij = w.s.it.g[lane][j];
                acc.x -= gij.x * xrj - gij.y * xij;
                acc.y -= gij.x * xij + gij.y * xrj;
            }
            w.s.it.u[lane] = acc;
        }
        __syncwarp();

        // (c) augmented complex columns [a_c | g | u], a_c = I + g*diag(var)
        ull c[8];
        if (lane < 16) {
            int j = lane & 7;
            if (lane < 8) {
                ull var2 = PK(var, var);
                #pragma unroll
                for (int i = 0; i < 8; i++)
                    c[i] = FMA2(*(const ull*)&w.s.it.g[i][j], var2,
                                PK((i == j) ? 1.f : 0.f, 0.f));
            } else {
                #pragma unroll
                for (int i = 0; i < 8; i++) c[i] = *(const ull*)&w.s.it.g[i][j];
            }
        } else if (lane == 16) {
            #pragma unroll
            for (int i = 0; i < 8; i++) c[i] = *(const ull*)&w.s.it.u[i];
        } else {
            #pragma unroll
            for (int i = 0; i < 8; i++) c[i] = 0ull;
        }

        // (d) 8x8 complex Gauss-Jordan (packed); lanes 8..16 become [W g | W u]
        #pragma unroll
        for (int k = 0; k < 8; k++) {
            float kr, ki; UPK(c[k], kr, ki);
            float dk = __shfl_sync(FULL, kr, k);     // pivot is real
            float invd = __fdividef(1.f, dk);
            c[k] = MUL2(c[k], PK(invd, invd));       // normalize row k
            float nr, ni; UPK(c[k], nr, ni);
            ull nxk = PK(-nr, -ni);                  // -(row k)
            ull nxk2 = PK(ni, -nr);                  // -(i * row k)
            #pragma unroll
            for (int i = 0; i < 8; i++) {
                if (i == k) continue;
                float xr, xi; UPK(c[i], xr, xi);
                float mr = __shfl_sync(FULL, xr, k);
                float mi = __shfl_sync(FULL, xi, k);
                c[i] = FMA2(PK(mr, mr), nxk, c[i]);
                c[i] = FMA2(PK(mi, mi), nxk2, c[i]);
            }
        }

        // (e) extract Mc_s = (Wg)[s][s] and Wu
        if (lane >= 8 && lane < 16) {
            int s = lane - 8;
            ull sel = 0ull;
            #pragma unroll
            for (int q = 0; q < 8; q++) if (q == s) sel = c[q];
            *(ull*)&w.s.it.Mc[s] = sel;
        }
        if (lane == 16) {
            #pragma unroll
            for (int s = 0; s < 8; s++) *(ull*)&w.s.it.Wu[s] = c[s];
        }
        __syncwarp();

        // (f) finalize + separable max-log demap (lane s = stream)
        if (lane < 8) {
            float2 Mc = w.s.it.Mc[lane];
            float2 Wu = w.s.it.Wu[lane];
            float mu = Mc.x;
            float vr = Wu.x + mre * Mc.x - mim * Mc.y;
            float vi = Wu.y + mre * Mc.y + mim * Mc.x;
            float invmu = __fdividef(1.f, mu);
            float xr_ = vr * invmu, xi_ = vi * invmu;
            float rho = mu * __fdividef(1.f, fmaxf(1.f - var * mu, EPS_));

            float q1 = rho * 0.1f;
            float c1 = 2.f * INVS10 * rho * xr_;
            float RE00 =        c1 -       q1;
            float RE01 =  3.f * c1 - 9.f * q1 + l2;
            float RE10 =       -c1 -       q1 + l0;
            float RE11 = -3.f * c1 - 9.f * q1 + l0 + l2;
            d0 = fmaxf(RE10, RE11) - fmaxf(RE00, RE01);
            d2 = fmaxf(RE01, RE11) - fmaxf(RE00, RE10);
            float c2 = 2.f * INVS10 * rho * xi_;
            float IM00 =        c2 -       q1;
            float IM01 =  3.f * c2 - 9.f * q1 + l3;
            float IM10 =       -c2 -       q1 + l1;
            float IM11 = -3.f * c2 - 9.f * q1 + l1 + l3;
            d1 = fmaxf(IM10, IM11) - fmaxf(IM00, IM01);
            d3 = fmaxf(IM01, IM11) - fmaxf(IM00, IM10);
        }

        if (iter == 0) {
            pa0 = d0; pa1 = d1; pa2 = d2; pa3 = d3;
            l0 = d0; l1 = d1; l2 = d2; l3 = d3;
        }
    }

    // ---------------- extrinsic output ----------------
    if (lane < 8) {
        float4 o = make_float4(d0 - pa0, d1 - pa1, d2 - pa2, d3 - pa3);
        *(float4*)(out + (size_t)b * 32 + lane * 4) = o;
    }
}

extern "C" void kernel_launch(void* const* d_in, const int* in_sizes, int n_in,
                              void* d_out, int out_size)
{
    const float* y_re  = (const float*)d_in[0];
    const float* y_im  = (const float*)d_in[1];
    const float* h_re  = (const float*)d_in[2];
    const float* h_im  = (const float*)d_in[3];
    const float* prior = (const float*)d_in[4];
    const float* s_re  = (const float*)d_in[5];
    const float* s_im  = (const float*)d_in[6];
    float* out = (float*)d_out;

    int nbatch = in_sizes[0] / 16;
    int blocks = (nbatch + WPB - 1) / WPB;
    mmse_pic_kernel<<<blocks, WPB * 32>>>(y_re, y_im, h_re, h_im, prior,
                                          s_re, s_im, out, nbatch);
}

// round 5
// speedup vs baseline: 2.3875x; 1.4369x over previous
#include <cuda_runtime.h>
#include <math.h>

#define FULL 0xffffffffu
#define INVS10 0.31622776601683794f   // 1/sqrt(10)
#define EPS_ 1e-4f

typedef unsigned long long ull;

__device__ __forceinline__ ull PK(float lo, float hi) {
    ull r; asm("mov.b64 %0, {%1,%2};" : "=l"(r) : "f"(lo), "f"(hi)); return r;
}
__device__ __forceinline__ void UPK(ull v, float& lo, float& hi) {
    asm("mov.b64 {%0,%1}, %2;" : "=f"(lo), "=f"(hi) : "l"(v));
}
__device__ __forceinline__ ull FMA2(ull a, ull b, ull c) {
    ull d; asm("fma.rn.f32x2 %0, %1, %2, %3;" : "=l"(d) : "l"(a), "l"(b), "l"(c)); return d;
}
__device__ __forceinline__ ull MUL2(ull a, ull b) {
    ull d; asm("mul.rn.f32x2 %0, %1, %2;" : "=l"(d) : "l"(a), "l"(b)); return d;
}

// Two batches per warp: batch = half-warp. All broadcasts use width-16 shfl,
// so one SHFL instruction serves both batches.
struct __align__(16) WarpSmem {
    union {
        float2 A[2][16][26];            // staging [S cols 0..15 | H 16..23 | y 24]
        struct {
            float2 HY[2][9][18];        // whitened cols, col-major padded
            float2 g[2][8][9];          // Gram (full, mirrored); col 8 = ymf
            float2 uu[2][8];            // ymf - g*x
            float2 Mc[2][8];            // (W g)[s][s]
            float2 Wu[2][8];            // (W u)[s]
        } it;
    } s;
};

__global__ __launch_bounds__(128)
void mmse_pic_kernel(const float* __restrict__ y_re, const float* __restrict__ y_im,
                     const float* __restrict__ h_re, const float* __restrict__ h_im,
                     const float* __restrict__ prior,
                     const float* __restrict__ s_re, const float* __restrict__ s_im,
                     float* __restrict__ out, int nbatch)
{
    const int warp  = threadIdx.x >> 5;
    const int lane  = threadIdx.x & 31;
    const int half  = lane >> 4;        // which batch in this warp
    const int hlane = lane & 15;

    int b = blockIdx.x * 8 + warp * 2 + half;
    if (b >= nbatch) b = nbatch - 1;    // benign duplicate on tail

    __shared__ WarpSmem ws[4];
    WarpSmem& w = ws[warp];

    // ---------------- coalesced staging of BOTH batches ----------------
    #pragma unroll
    for (int bb = 0; bb < 2; bb++) {
        int bg = blockIdx.x * 8 + warp * 2 + bb;
        if (bg >= nbatch) bg = nbatch - 1;
        const float* sre = s_re + (size_t)bg * 256;
        const float* sim = s_im + (size_t)bg * 256;
        #pragma unroll
        for (int t = lane; t < 256; t += 32)
            w.s.A[bb][t >> 4][t & 15] = make_float2(sre[t], sim[t]);
        const float* hre = h_re + (size_t)bg * 128;
        const float* him = h_im + (size_t)bg * 128;
        #pragma unroll
        for (int t = lane; t < 128; t += 32)
            w.s.A[bb][t >> 3][16 + (t & 7)] = make_float2(hre[t], him[t]);
        if (lane < 16)
            w.s.A[bb][lane][24] = make_float2(y_re[(size_t)bg * 16 + lane],
                                              y_im[(size_t)bg * 16 + lane]);
    }
    // prior LLRs (per-stream, hlane<8)
    float l0 = 0.f, l1 = 0.f, l2 = 0.f, l3 = 0.f;
    if (hlane < 8) {
        float4 p = *(const float4*)(prior + (size_t)b * 32 + hlane * 4);
        l0 = p.x; l1 = p.y; l2 = p.z; l3 = p.w;
    }
    __syncwarp();

    // ---------------- per-lane columns: vS = S col hlane, vH = [H|y] col ----------------
    ull vS[16], vH[16];
    {
        int ch = (hlane < 8) ? (16 + hlane) : 24;   // hlane 8..15 dup y (dead for 9..15)
        #pragma unroll
        for (int m = 0; m < 16; m++) {
            vS[m] = *(const ull*)&w.s.A[half][m][hlane];
            vH[m] = *(const ull*)&w.s.A[half][m][ch];
        }
    }
    __syncwarp();   // A dead after this

    // ---------------- forward elimination on [S | H | y] (LDL^H whitening) ----------------
    #pragma unroll
    for (int k = 0; k < 16; k++) {
        float skr, ski; UPK(vS[k], skr, ski);
        float dk = __shfl_sync(FULL, skr, k, 16);
        float invd = __fdividef(1.0f, dk);
        float rsd = rsqrtf(dk);
        ull nii = PK(-invd, -invd);
        ull wS = MUL2(vS[k], nii);           // -invd * vS[k]
        float wsr, wsi; UPK(wS, wsr, wsi);
        ull wS2 = PK(-wsi, wsr);
        ull wH = MUL2(vH[k], nii);
        float whr, whi; UPK(wH, whr, whi);
        ull wH2 = PK(-whi, whr);
        #pragma unroll
        for (int i = k + 1; i < 16; i++) {
            float xr, xi; UPK(vS[i], xr, xi);
            float mr = __shfl_sync(FULL, xr, k, 16);   // A[i][k] raw, per half-warp
            float mi = __shfl_sync(FULL, xi, k, 16);
            ull mr2 = PK(mr, mr), mi2 = PK(mi, mi);
            vS[i] = FMA2(mr2, wS, vS[i]);
            vS[i] = FMA2(mi2, wS2, vS[i]);
            vH[i] = FMA2(mr2, wH, vH[i]);
            vH[i] = FMA2(mi2, wH2, vH[i]);
        }
        vH[k] = MUL2(vH[k], PK(rsd, rsd));   // whitened row k (S cols never need it)
    }

    // write whitened [H | y] columns (float4)
    if (hlane < 9) {
        #pragma unroll
        for (int m = 0; m < 16; m += 2) {
            float a0, b0, a1, b1;
            UPK(vH[m], a0, b0); UPK(vH[m + 1], a1, b1);
            *(float4*)&w.s.it.HY[half][hlane][m] = make_float4(a0, b0, a1, b1);
        }
    }
    __syncwarp();

    // ---------------- Gram (Hermitian: 36 triangle + 8 ymf per batch, mirrored) ----------
    #pragma unroll
    for (int r = 0; r < 3; r++) {
        int t = hlane + 16 * r;
        if (t < 44) {
            int i, j;
            if (t < 36) {
                j = (int)((sqrtf(8.f * t + 1.f) - 1.f) * 0.5f);
                i = t - ((j * (j + 1)) >> 1);
            } else { j = 8; i = t - 36; }
            float re = 0.f, im = 0.f;
            #pragma unroll
            for (int m = 0; m < 16; m += 2) {
                float4 a4 = *(const float4*)&w.s.it.HY[half][i][m];
                float4 c4 = *(const float4*)&w.s.it.HY[half][j][m];
                re = fmaf(a4.x, c4.x, fmaf(a4.y, c4.y, re));
                im = fmaf(a4.x, c4.y, fmaf(-a4.y, c4.x, im));
                re = fmaf(a4.z, c4.z, fmaf(a4.w, c4.w, re));
                im = fmaf(a4.z, c4.w, fmaf(-a4.w, c4.z, im));
            }
            w.s.it.g[half][i][j] = make_float2(re, im);
            if (j < 8 && i != j)
                w.s.it.g[half][j][i] = make_float2(re, -im);   // Hermitian mirror
        }
    }
    __syncwarp();

    // ---------------- MMSE-PIC iterations ----------------
    float d0 = 0.f, d1 = 0.f, d2 = 0.f, d3 = 0.f;
    float pa0 = 0.f, pa1 = 0.f, pa2 = 0.f, pa3 = 0.f;

    #pragma unroll 1
    for (int iter = 0; iter < 2; iter++) {
        // (a) soft-symbol moments (uniform; garbage at hlane>=8, unused)
        float s0 = __fdividef(1.f, 1.f + __expf(-l0));
        float s1 = __fdividef(1.f, 1.f + __expf(-l1));
        float s2 = __fdividef(1.f, 1.f + __expf(-l2));
        float s3 = __fdividef(1.f, 1.f + __expf(-l3));
        float mre = (1.f - 2.f * s0) * (1.f + 2.f * s2) * INVS10;
        float mim = (1.f - 2.f * s1) * (1.f + 2.f * s3) * INVS10;
        float var = (2.f + 8.f * (s2 + s3)) * 0.1f - (mre * mre + mim * mim);

        // (b) u = ymf - g @ x_hat  (hlane<8; one shfl serves both batches, width 8)
        if (hlane < 8) {
            float2 acc = w.s.it.g[half][hlane][8];
            #pragma unroll
            for (int j = 0; j < 8; j++) {
                float xrj = __shfl_sync(0x00FF00FFu, mre, j, 8);
                float xij = __shfl_sync(0x00FF00FFu, mim, j, 8);
                float2 gij = w.s.it.g[half][hlane][j];
                acc.x -= gij.x * xrj - gij.y * xij;
                acc.y -= gij.x * xij + gij.y * xrj;
            }
            w.s.it.uu[half][hlane] = acc;
        }
        __syncwarp();

        // (c) GJ columns: hlane<8 -> a_c col hlane; hlane>=8 -> g col (hlane-8).
        //     Second column c2: u at hlane 0, zeros elsewhere (uniform updates).
        ull c1[8], c2[8];
        if (hlane < 8) {
            ull var2 = PK(var, var);
            #pragma unroll
            for (int i = 0; i < 8; i++)
                c1[i] = FMA2(*(const ull*)&w.s.it.g[half][i][hlane], var2,
                             PK((i == hlane) ? 1.f : 0.f, 0.f));
        } else {
            int j = hlane - 8;
            #pragma unroll
            for (int i = 0; i < 8; i++) c1[i] = *(const ull*)&w.s.it.g[half][i][j];
        }
        #pragma unroll
        for (int i = 0; i < 8; i++) c2[i] = 0ull;
        if (hlane == 0) {
            #pragma unroll
            for (int i = 0; i < 8; i++) c2[i] = *(const ull*)&w.s.it.uu[half][i];
        }

        // (d) 8x8 complex Gauss-Jordan (width-16 shfl serves both batches)
        #pragma unroll
        for (int k = 0; k < 8; k++) {
            float kr, ki; UPK(c1[k], kr, ki);
            float dk = __shfl_sync(FULL, kr, k, 16);    // pivot real
            float invd = __fdividef(1.f, dk);
            ull iv = PK(invd, invd);
            c1[k] = MUL2(c1[k], iv);
            c2[k] = MUL2(c2[k], iv);
            float nr, ni; UPK(c1[k], nr, ni);
            ull n1 = PK(-nr, -ni), n1b = PK(ni, -nr);
            float qr, qi; UPK(c2[k], qr, qi);
            ull n2 = PK(-qr, -qi), n2b = PK(qi, -qr);
            #pragma unroll
            for (int i = 0; i < 8; i++) {
                if (i == k) continue;
                float xr, xi; UPK(c1[i], xr, xi);
                float mr = __shfl_sync(FULL, xr, k, 16);
                float mi = __shfl_sync(FULL, xi, k, 16);
                ull mr2 = PK(mr, mr), mi2 = PK(mi, mi);
                c1[i] = FMA2(mr2, n1, c1[i]);
                c1[i] = FMA2(mi2, n1b, c1[i]);
                c2[i] = FMA2(mr2, n2, c2[i]);
                c2[i] = FMA2(mi2, n2b, c2[i]);
            }
        }

        // (e) extract Mc_s = (Wg)[s][s] (hlane 8+s) and Wu (hlane 0's c2)
        if (hlane >= 8) {
            int s2i = hlane - 8;
            ull sel = 0ull;
            #pragma unroll
            for (int q = 0; q < 8; q++) if (q == s2i) sel = c1[q];
            *(ull*)&w.s.it.Mc[half][s2i] = sel;
        }
        if (hlane == 0) {
            #pragma unroll
            for (int s = 0; s < 8; s++) *(ull*)&w.s.it.Wu[half][s] = c2[s];
        }
        __syncwarp();

        // (f) finalize + separable max-log demap (hlane = stream)
        if (hlane < 8) {
            float2 Mc = w.s.it.Mc[half][hlane];
            float2 Wu = w.s.it.Wu[half][hlane];
            float mu = Mc.x;
            float vr = Wu.x + mre * Mc.x - mim * Mc.y;
            float vi = Wu.y + mre * Mc.y + mim * Mc.x;
            float invmu = __fdividef(1.f, mu);
            float xr_ = vr * invmu, xi_ = vi * invmu;
            float rho = mu * __fdividef(1.f, fmaxf(1.f - var * mu, EPS_));

            float q1 = rho * 0.1f;
            float c1d = 2.f * INVS10 * rho * xr_;
            float RE00 =        c1d -       q1;
            float RE01 =  3.f * c1d - 9.f * q1 + l2;
            float RE10 =       -c1d -       q1 + l0;
            float RE11 = -3.f * c1d - 9.f * q1 + l0 + l2;
            d0 = fmaxf(RE10, RE11) - fmaxf(RE00, RE01);
            d2 = fmaxf(RE01, RE11) - fmaxf(RE00, RE10);
            float c2d = 2.f * INVS10 * rho * xi_;
            float IM00 =        c2d -       q1;
            float IM01 =  3.f * c2d - 9.f * q1 + l3;
            float IM10 =       -c2d -       q1 + l1;
            float IM11 = -3.f * c2d - 9.f * q1 + l1 + l3;
            d1 = fmaxf(IM10, IM11) - fmaxf(IM00, IM01);
            d3 = fmaxf(IM01, IM11) - fmaxf(IM00, IM10);
        }

        if (iter == 0) {
            pa0 = d0; pa1 = d1; pa2 = d2; pa3 = d3;
            l0 = d0; l1 = d1; l2 = d2; l3 = d3;
        }
    }

    // ---------------- extrinsic output ----------------
    if (hlane < 8) {
        float4 o = make_float4(d0 - pa0, d1 - pa1, d2 - pa2, d3 - pa3);
        *(float4*)(out + (size_t)b * 32 + hlane * 4) = o;
    }
}

extern "C" void kernel_launch(void* const* d_in, const int* in_sizes, int n_in,
                              void* d_out, int out_size)
{
    const float* y_re  = (const float*)d_in[0];
    const float* y_im  = (const float*)d_in[1];
    const float* h_re  = (const float*)d_in[2];
    const float* h_im  = (const float*)d_in[3];
    const float* prior = (const float*)d_in[4];
    const float* s_re  = (const float*)d_in[5];
    const float* s_im  = (const float*)d_in[6];
    float* out = (float*)d_out;

    int nbatch = in_sizes[0] / 16;
    int blocks = (nbatch + 7) / 8;      // 8 batches per 128-thread block
    mmse_pic_kernel<<<blocks, 128>>>(y_re, y_im, h_re, h_im, prior,
                                     s_re, s_im, out, nbatch);
}